// round 2
// baseline (speedup 1.0000x reference)
#include <cuda_runtime.h>
#include <cstdint>
#include <cstddef>

// Problem constants (fixed by the reference setup)
#define BD 8      // batch
#define LL 2048   // sequence length
#define DM 1024   // d_model
#define DKK 1024  // d_k

// Scratch: Q, K, V projections (allocation-free: __device__ globals).
// Plus a fallback scores buffer in case d_out does not include attention.
__device__ float g_QKV[3ull * BD * LL * DKK];
__device__ float g_S[(size_t)BD * LL * LL];

__device__ __forceinline__ float to_tf32(float x) {
    uint32_t r;
    asm("cvt.rna.tf32.f32 %0, %1;" : "=r"(r) : "f"(x));
    return __uint_as_float(r);
}

__device__ __forceinline__ void mma_m16n8k8(float d[4], const uint32_t a[4], const uint32_t b[2]) {
    asm volatile(
        "mma.sync.aligned.m16n8k8.row.col.f32.tf32.tf32.f32 "
        "{%0,%1,%2,%3},{%4,%5,%6,%7},{%8,%9},{%0,%1,%2,%3};\n"
        : "+f"(d[0]), "+f"(d[1]), "+f"(d[2]), "+f"(d[3])
        : "r"(a[0]), "r"(a[1]), "r"(a[2]), "r"(a[3]), "r"(b[0]), "r"(b[1]));
}

// Generic tiled GEMM: C[M,N] = (A[M,K] * op(B)) with optional bias+scale epilogue.
// B_NK:       B stored row-major [N,K] (i.e. computes A*B^T) — QKV weights, K matrix.
// !B_NK:      B stored row-major [K,N] — the V matrix in AV.
// LOWER_ONLY: skip tiles strictly above the diagonal (scores; softmax ignores them).
// K_TRI:      K-loop bounded at the block-row diagonal (AV: attention is lower-tri).
template <bool B_NK, bool LOWER_ONLY, bool K_TRI>
__global__ void __launch_bounds__(256) gemm_tf32(
    const float* __restrict__ A, const float* __restrict__ B,
    float* __restrict__ C, const float* __restrict__ bias,
    int M, int N, int K, float scale,
    size_t bsA, size_t bsB, size_t bsC)
{
    constexpr int BM = 128, BN = 128, BK = 32, SP = BK + 4;  // smem stride 36 -> conflict-free frags
    __shared__ float sA[BM * SP];
    __shared__ float sB[BN * SP];

    const int bn = blockIdx.x, bm = blockIdx.y, bz = blockIdx.z;
    if (LOWER_ONLY && bn > bm) return;
    A += (size_t)bz * bsA;
    B += (size_t)bz * bsB;
    C += (size_t)bz * bsC;

    int Keff = K;
    if (K_TRI) {
        int kb = (bm + 1) * BM;
        Keff = kb < K ? kb : K;
    }

    const int tid = threadIdx.x;
    const int lane = tid & 31, wid = tid >> 5;
    const int wm = wid & 1, wn = wid >> 1;  // warp grid 2(m) x 4(n), warp tile 64x32

    float d[4][4][4];
#pragma unroll
    for (int i = 0; i < 4; i++)
#pragma unroll
        for (int j = 0; j < 4; j++)
#pragma unroll
            for (int r = 0; r < 4; r++) d[i][j][r] = 0.f;

    const float* Abase = A + (size_t)(bm * BM) * K;

    for (int kt = 0; kt < Keff; kt += BK) {
        // ---- load A tile [128 x 32], row-major, convert to tf32 (rna) ----
#pragma unroll
        for (int i = 0; i < 4; i++) {
            int f = tid + i * 256;
            int row = f >> 3, c4 = (f & 7) << 2;
            float4 v = *reinterpret_cast<const float4*>(Abase + (size_t)row * K + kt + c4);
            float4 t;
            t.x = to_tf32(v.x); t.y = to_tf32(v.y); t.z = to_tf32(v.z); t.w = to_tf32(v.w);
            *reinterpret_cast<float4*>(&sA[row * SP + c4]) = t;
        }
        if (B_NK) {
            const float* Bbase = B + (size_t)(bn * BN) * K;
#pragma unroll
            for (int i = 0; i < 4; i++) {
                int f = tid + i * 256;
                int row = f >> 3, c4 = (f & 7) << 2;
                float4 v = *reinterpret_cast<const float4*>(Bbase + (size_t)row * K + kt + c4);
                float4 t;
                t.x = to_tf32(v.x); t.y = to_tf32(v.y); t.z = to_tf32(v.z); t.w = to_tf32(v.w);
                *reinterpret_cast<float4*>(&sB[row * SP + c4]) = t;
            }
        } else {
            // B is [K,N]; load tile [32 x 128] and transpose into sB[n][k]
            const float* Bbase = B + (size_t)kt * N + bn * BN;
#pragma unroll
            for (int i = 0; i < 4; i++) {
                int f = tid + i * 256;
                int kr = f >> 5, n4 = (f & 31) << 2;
                float4 v = *reinterpret_cast<const float4*>(Bbase + (size_t)kr * N + n4);
                sB[(n4 + 0) * SP + kr] = to_tf32(v.x);
                sB[(n4 + 1) * SP + kr] = to_tf32(v.y);
                sB[(n4 + 2) * SP + kr] = to_tf32(v.z);
                sB[(n4 + 3) * SP + kr] = to_tf32(v.w);
            }
        }
        __syncthreads();

#pragma unroll
        for (int kk = 0; kk < BK; kk += 8) {
            uint32_t a[4][4], b[4][2];
#pragma unroll
            for (int mf = 0; mf < 4; mf++) {
                int r0 = wm * 64 + mf * 16 + (lane >> 2);
                int c0 = kk + (lane & 3);
                a[mf][0] = __float_as_uint(sA[r0 * SP + c0]);
                a[mf][1] = __float_as_uint(sA[(r0 + 8) * SP + c0]);
                a[mf][2] = __float_as_uint(sA[r0 * SP + c0 + 4]);
                a[mf][3] = __float_as_uint(sA[(r0 + 8) * SP + c0 + 4]);
            }
#pragma unroll
            for (int nf = 0; nf < 4; nf++) {
                int cc = wn * 32 + nf * 8 + (lane >> 2);
                int rr = kk + (lane & 3);
                b[nf][0] = __float_as_uint(sB[cc * SP + rr]);
                b[nf][1] = __float_as_uint(sB[cc * SP + rr + 4]);
            }
#pragma unroll
            for (int mf = 0; mf < 4; mf++)
#pragma unroll
                for (int nf = 0; nf < 4; nf++)
                    mma_m16n8k8(d[mf][nf], a[mf], b[nf]);
        }
        __syncthreads();
    }

    // ---- epilogue: C = (acc + bias) * scale ----
#pragma unroll
    for (int mf = 0; mf < 4; mf++) {
        int r0 = bm * BM + wm * 64 + mf * 16 + (lane >> 2);
#pragma unroll
        for (int nf = 0; nf < 4; nf++) {
            int c0 = bn * BN + wn * 32 + nf * 8 + ((lane & 3) << 1);
            float b0 = bias ? bias[c0] : 0.f;
            float b1 = bias ? bias[c0 + 1] : 0.f;
            float2 v0 = make_float2((d[mf][nf][0] + b0) * scale, (d[mf][nf][1] + b1) * scale);
            float2 v1 = make_float2((d[mf][nf][2] + b0) * scale, (d[mf][nf][3] + b1) * scale);
            *reinterpret_cast<float2*>(&C[(size_t)r0 * N + c0]) = v0;
            *reinterpret_cast<float2*>(&C[(size_t)(r0 + 8) * N + c0]) = v1;
        }
    }
}

// Column-wise softmax (reference uses softmax over axis=1, i.e. over the query
// index l, per key column m). Masked entries (m > l) get exactly 0.
// Block: 256 threads = 64 columns x 4 row segments. Grid: (L/64, B).
__global__ void __launch_bounds__(256) softmax_col(
    const float* __restrict__ S, float* __restrict__ Aout, int L)
{
    const int b = blockIdx.y;
    const float* Sb = S + (size_t)b * L * L;
    float* Ab = Aout + (size_t)b * L * L;
    const int tid = threadIdx.x;
    const int c = blockIdx.x * 64 + (tid & 63);
    const int seg = tid >> 6;
    const int chunk = L >> 2;
    const int l0 = seg * chunk, l1 = l0 + chunk;

    float mx = -1e30f, sum = 0.f;
    for (int l = l0; l < l1; l++) {
        float x = Sb[(size_t)l * L + c];
        if (l >= c) {
            float m2 = fmaxf(mx, x);
            sum = sum * __expf(mx - m2) + __expf(x - m2);
            mx = m2;
        }
    }

    __shared__ float sm[4][64], ss[4][64];
    sm[seg][tid & 63] = mx;
    ss[seg][tid & 63] = sum;
    __syncthreads();

    float M = fmaxf(fmaxf(sm[0][tid & 63], sm[1][tid & 63]),
                    fmaxf(sm[2][tid & 63], sm[3][tid & 63]));
    float Z = 0.f;
#pragma unroll
    for (int s = 0; s < 4; s++) Z += ss[s][tid & 63] * __expf(sm[s][tid & 63] - M);
    float inv = 1.f / Z;

    for (int l = l0; l < l1; l++) {
        float x = Sb[(size_t)l * L + c];
        Ab[(size_t)l * L + c] = (l >= c) ? __expf(x - M) * inv : 0.f;
    }
}

extern "C" void kernel_launch(void* const* d_in, const int* in_sizes, int n_in,
                              void* d_out, int out_size)
{
    const float* src = (const float*)d_in[0];
    const float* Wq  = (const float*)d_in[1];
    const float* bq  = (const float*)d_in[2];
    const float* Wk  = (const float*)d_in[3];
    const float* bk  = (const float*)d_in[4];
    const float* Wv  = (const float*)d_in[5];
    const float* bv  = (const float*)d_in[6];

    float* out = (float*)d_out;
    const size_t out_elems = (size_t)BD * LL * DKK;
    const size_t attn_elems = (size_t)BD * LL * LL;

    float* qkv = nullptr;
    cudaGetSymbolAddress((void**)&qkv, g_QKV);
    float* Sbuf = nullptr;
    cudaGetSymbolAddress((void**)&Sbuf, g_S);

    float* Q  = qkv;
    float* Km = qkv + (size_t)BD * LL * DKK;
    float* Vm = qkv + 2ull * BD * LL * DKK;

    // Attention destination: into d_out if it holds (output, attention), else scratch.
    float* attn_dst = ((size_t)out_size >= out_elems + attn_elems) ? (out + out_elems) : Sbuf;

    dim3 blk(256);

    // QKV projections: q gets the 1/sqrt(d_k)=1/32 score scale folded in (bias scaled too,
    // which matches (x Wq^T + bq)/32 inside the score product).
    gemm_tf32<true, false, false><<<dim3(DKK / 128, (BD * LL) / 128, 1), blk>>>(
        src, Wq, Q, bq, BD * LL, DKK, DM, 1.f / 32.f, 0, 0, 0);
    gemm_tf32<true, false, false><<<dim3(DKK / 128, (BD * LL) / 128, 1), blk>>>(
        src, Wk, Km, bk, BD * LL, DKK, DM, 1.f, 0, 0, 0);
    gemm_tf32<true, false, false><<<dim3(DKK / 128, (BD * LL) / 128, 1), blk>>>(
        src, Wv, Vm, bv, BD * LL, DKK, DM, 1.f, 0, 0, 0);

    // scores = (Q/32) @ K^T, lower-triangular tiles only, into scratch S
    gemm_tf32<true, true, false><<<dim3(LL / 128, LL / 128, BD), blk>>>(
        Q, Km, Sbuf, nullptr, LL, LL, DKK, 1.f,
        (size_t)LL * DKK, (size_t)LL * DKK, (size_t)LL * LL);

    // column softmax (axis=1) with causal mask handled structurally; writes zeros above diag
    softmax_col<<<dim3(LL / 64, BD), blk>>>(Sbuf, attn_dst, LL);

    // output = attention @ V, with K-loop bounded at the diagonal (attention lower-tri)
    gemm_tf32<false, false, true><<<dim3(DKK / 128, LL / 128, BD), blk>>>(
        attn_dst, Vm, out, nullptr, LL, DKK, LL, 1.f,
        (size_t)LL * LL, (size_t)LL * DKK, (size_t)LL * DKK);
}